// round 8
// baseline (speedup 1.0000x reference)
#include <cuda_runtime.h>
#include <cstddef>

// ---------------------------------------------------------------------------
// GATv2 x2 on GB300.  kernel_launch = kernel launches ONLY.  (tcgen05 is not
// available: harness ptxas targets sm_103 without the 'a' feature set.)
//   1. CSR build by dst (4-way unrolled atomics)
//   2. xl1/xr1 GEMMs (reg-blocked f32x2, launch_bounds(256,4))
//   3. agg layer1 (warp/dst, 8-edge unroll) -> g_h
//   4. xl2/xr2 GEMMs
//   5. agg layer2 -> d_out
// ---------------------------------------------------------------------------

#define NMAX 100000
#define EMAX 1700032

__device__ float g_xl1[NMAX * 128];
__device__ float g_xr1[NMAX * 128];
__device__ float g_h  [NMAX * 128];
__device__ float g_xl2[NMAX * 64];
__device__ float g_xr2[NMAX * 64];
__device__ int   g_deg[NMAX];
__device__ int   g_cnt[NMAX];
__device__ int   g_rowptr[NMAX + 1];
__device__ int   g_col[EMAX];

// --------------------------- CSR build -------------------------------------

__global__ void k_zero(int n) {
    int i = blockIdx.x * blockDim.x + threadIdx.x;
    if (i < n) { g_deg[i] = 0; g_cnt[i] = 0; }
}

// 4 independent atomics per thread -> MLP 4 (latency-bound kernel)
__global__ void k_count(const int* __restrict__ dstE, int E, int total) {
    int i0 = (blockIdx.x * blockDim.x + threadIdx.x) * 4;
    #pragma unroll
    for (int u = 0; u < 4; u++) {
        int i = i0 + u;
        if (i < total) {
            int d = (i < E) ? dstE[i] : (i - E);
            atomicAdd(&g_deg[d], 1);
        }
    }
}

__global__ void k_scan(int n) {
    __shared__ int wsum[32];
    __shared__ int carry;
    int t = threadIdx.x;
    if (t == 0) carry = 0;
    __syncthreads();
    for (int base = 0; base < n; base += 1024) {
        int i = base + t;
        int v = (i < n) ? g_deg[i] : 0;
        int x = v;
        #pragma unroll
        for (int off = 1; off < 32; off <<= 1) {
            int y = __shfl_up_sync(0xffffffffu, x, off);
            if ((t & 31) >= off) x += y;
        }
        if ((t & 31) == 31) wsum[t >> 5] = x;
        __syncthreads();
        if (t < 32) {
            int w = wsum[t];
            #pragma unroll
            for (int off = 1; off < 32; off <<= 1) {
                int y = __shfl_up_sync(0xffffffffu, w, off);
                if (t >= off) w += y;
            }
            wsum[t] = w;
        }
        __syncthreads();
        int incl = x + ((t >= 32) ? wsum[(t >> 5) - 1] : 0);
        if (i < n) g_rowptr[i] = incl - v + carry;
        __syncthreads();
        if (t == 1023) carry += incl;
        __syncthreads();
    }
    if (t == 0) g_rowptr[n] = carry;
}

__global__ void k_scatter(const int* __restrict__ srcE,
                          const int* __restrict__ dstE, int E, int total) {
    int i0 = (blockIdx.x * blockDim.x + threadIdx.x) * 4;
    #pragma unroll
    for (int u = 0; u < 4; u++) {
        int i = i0 + u;
        if (i < total) {
            int s, d;
            if (i < E) { s = srcE[i]; d = dstE[i]; }
            else       { s = i - E; d = s; }
            int pos = g_rowptr[d] + atomicAdd(&g_cnt[d], 1);
            g_col[pos] = s;
        }
    }
}

// --------------------------- dense GEMM ------------------------------------
// Y[n,NOUT] = X[n,128] @ W[128,NOUT] + B.
// Thread tile 4 rows x 8 cols; launch_bounds(256,4) -> 63 regs, 4 blocks/SM.

template<int DSTSEL>
__device__ __forceinline__ float* dst_buf() {
    if constexpr (DSTSEL == 0) return g_xl1;
    else if constexpr (DSTSEL == 1) return g_xr1;
    else if constexpr (DSTSEL == 2) return g_xl2;
    else return g_xr2;
}

template<int XSEL, int DSTSEL, int NOUT>
__global__ void __launch_bounds__(256, 4)
k_gemm(const float* __restrict__ Xarg,
       const float* __restrict__ W,
       const float* __restrict__ Bias, int n) {
    constexpr int K = 128, KC = 64, NB = 64, TPR = 8;
    constexpr int RG = 256 / TPR;
    constexpr int R = 4;
    constexpr int ROWS = RG * R;                         // 128 rows/block
    __shared__ float sW[KC][NB];          // 16 KB
    __shared__ float sx[ROWS][KC + 1];    // 33.3 KB

    const float* X = (XSEL == 0) ? Xarg : g_h;
    float* Y = dst_buf<DSTSEL>();

    int tid = threadIdx.x;
    int colOff = blockIdx.y * NB;
    int c0 = (tid % TPR) * 4;
    int rg = tid / TPR;
    int base = blockIdx.x * ROWS;

    float4 bv0 = *reinterpret_cast<const float4*>(Bias + colOff + c0);
    float4 bv1 = *reinterpret_cast<const float4*>(Bias + colOff + c0 + 32);
    unsigned long long a0[R][2], a1[R][2];
    #pragma unroll
    for (int r = 0; r < R; r++) {
        asm("mov.b64 %0, {%1,%2};" : "=l"(a0[r][0]) : "f"(bv0.x), "f"(bv0.y));
        asm("mov.b64 %0, {%1,%2};" : "=l"(a0[r][1]) : "f"(bv0.z), "f"(bv0.w));
        asm("mov.b64 %0, {%1,%2};" : "=l"(a1[r][0]) : "f"(bv1.x), "f"(bv1.y));
        asm("mov.b64 %0, {%1,%2};" : "=l"(a1[r][1]) : "f"(bv1.z), "f"(bv1.w));
    }

    for (int kc = 0; kc < K; kc += KC) {
        __syncthreads();
        for (int i = tid; i < KC * NB / 4; i += 256) {
            int krow = (i * 4) / NB;
            int col  = (i * 4) % NB;
            *reinterpret_cast<float4*>(&sW[krow][col]) =
                *reinterpret_cast<const float4*>(W + (size_t)(kc + krow) * NOUT + colOff + col);
        }
        for (int i = tid; i < ROWS * (KC / 4); i += 256) {
            int r  = i / (KC / 4);
            int kk = (i % (KC / 4)) * 4;
            int row = base + r;
            float4 v = (row < n)
                ? *reinterpret_cast<const float4*>(X + (size_t)row * K + kc + kk)
                : make_float4(0.f, 0.f, 0.f, 0.f);
            sx[r][kk] = v.x; sx[r][kk+1] = v.y; sx[r][kk+2] = v.z; sx[r][kk+3] = v.w;
        }
        __syncthreads();
        #pragma unroll
        for (int k = 0; k < KC; k++) {
            ulonglong2 w0 = *reinterpret_cast<const ulonglong2*>(&sW[k][c0]);
            ulonglong2 w1 = *reinterpret_cast<const ulonglong2*>(&sW[k][c0 + 32]);
            #pragma unroll
            for (int r = 0; r < R; r++) {
                float xv = sx[rg * R + r][k];
                unsigned long long x2;
                asm("mov.b64 %0, {%1,%1};" : "=l"(x2) : "f"(xv));
                asm("fma.rn.f32x2 %0, %1, %2, %0;" : "+l"(a0[r][0]) : "l"(x2), "l"(w0.x));
                asm("fma.rn.f32x2 %0, %1, %2, %0;" : "+l"(a0[r][1]) : "l"(x2), "l"(w0.y));
                asm("fma.rn.f32x2 %0, %1, %2, %0;" : "+l"(a1[r][0]) : "l"(x2), "l"(w1.x));
                asm("fma.rn.f32x2 %0, %1, %2, %0;" : "+l"(a1[r][1]) : "l"(x2), "l"(w1.y));
            }
        }
    }

    #pragma unroll
    for (int r = 0; r < R; r++) {
        int row = base + rg * R + r;
        if (row < n) {
            float t0, t1, t2, t3;
            asm("mov.b64 {%0,%1}, %2;" : "=f"(t0), "=f"(t1) : "l"(a0[r][0]));
            asm("mov.b64 {%0,%1}, %2;" : "=f"(t2), "=f"(t3) : "l"(a0[r][1]));
            *reinterpret_cast<float4*>(Y + (size_t)row * NOUT + colOff + c0) =
                make_float4(t0, t1, t2, t3);
            asm("mov.b64 {%0,%1}, %2;" : "=f"(t0), "=f"(t1) : "l"(a1[r][0]));
            asm("mov.b64 {%0,%1}, %2;" : "=f"(t2), "=f"(t3) : "l"(a1[r][1]));
            *reinterpret_cast<float4*>(Y + (size_t)row * NOUT + colOff + c0 + 32) =
                make_float4(t0, t1, t2, t3);
        }
    }
}

// --------------------------- GATv2 aggregation ------------------------------
// Warp per destination node; 8 gathers in flight per iteration (MLP 8).
// Scores are O(+-10) (glorot x unit-normal): exp without max-pass is safe.

__device__ __forceinline__ float lrelu(float e) {
    return (e > 0.f) ? e : 0.2f * e;
}

__global__ void k_agg1(const float* __restrict__ att, const float* __restrict__ bias,
                       int n) {
    int v    = (blockIdx.x * blockDim.x + threadIdx.x) >> 5;
    int lane = threadIdx.x & 31;
    if (v >= n) return;

    const float4* xl4 = reinterpret_cast<const float4*>(g_xl1);
    float4 xrv  = *reinterpret_cast<const float4*>(g_xr1 + (size_t)v * 128 + lane * 4);
    float4 attv = *reinterpret_cast<const float4*>(att + lane * 4);
    float4 acc  = make_float4(0.f, 0.f, 0.f, 0.f);
    float  den  = 0.f;

    int s0 = g_rowptr[v], s1 = g_rowptr[v + 1];

    auto score = [&](const float4& xv) -> float {
        float s;
        s = lrelu(xv.x + xrv.x) * attv.x;
        s = fmaf(lrelu(xv.y + xrv.y), attv.y, s);
        s = fmaf(lrelu(xv.z + xrv.z), attv.z, s);
        s = fmaf(lrelu(xv.w + xrv.w), attv.w, s);
        s += __shfl_xor_sync(0xffffffffu, s, 1);
        s += __shfl_xor_sync(0xffffffffu, s, 2);
        s += __shfl_xor_sync(0xffffffffu, s, 4);
        return __expf(s);
    };
    auto accum = [&](const float4& xv, float p) {
        den += p;
        acc.x = fmaf(p, xv.x, acc.x);
        acc.y = fmaf(p, xv.y, acc.y);
        acc.z = fmaf(p, xv.z, acc.z);
        acc.w = fmaf(p, xv.w, acc.w);
    };

    int j = s0;
    for (; j + 8 <= s1; j += 8) {
        float4 xv[8];
        #pragma unroll
        for (int u = 0; u < 8; u++) {
            int src = g_col[j + u];
            xv[u] = __ldg(&xl4[(size_t)src * 32 + lane]);
        }
        float p[8];
        #pragma unroll
        for (int u = 0; u < 8; u++) p[u] = score(xv[u]);
        #pragma unroll
        for (int u = 0; u < 8; u++) accum(xv[u], p[u]);
    }
    for (; j < s1; j++) {
        int src = g_col[j];
        float4 xv = __ldg(&xl4[(size_t)src * 32 + lane]);
        accum(xv, score(xv));
    }

    float4 bv = *reinterpret_cast<const float4*>(bias + lane * 4);
    float inv = 1.f / den;
    float4 r;
    r.x = fmaxf(fmaf(acc.x, inv, bv.x), 0.f);
    r.y = fmaxf(fmaf(acc.y, inv, bv.y), 0.f);
    r.z = fmaxf(fmaf(acc.z, inv, bv.z), 0.f);
    r.w = fmaxf(fmaf(acc.w, inv, bv.w), 0.f);
    *reinterpret_cast<float4*>(g_h + (size_t)v * 128 + lane * 4) = r;
}

__global__ void k_agg2(const float* __restrict__ att, const float* __restrict__ bias,
                       float* __restrict__ out, int n) {
    int v    = (blockIdx.x * blockDim.x + threadIdx.x) >> 5;
    int lane = threadIdx.x & 31;
    if (v >= n) return;

    const float2* xl2 = reinterpret_cast<const float2*>(g_xl2);
    float2 xrv  = *reinterpret_cast<const float2*>(g_xr2 + (size_t)v * 64 + lane * 2);
    float2 attv = *reinterpret_cast<const float2*>(att + lane * 2);
    float2 acc  = make_float2(0.f, 0.f);
    float  den  = 0.f;

    int s0 = g_rowptr[v], s1 = g_rowptr[v + 1];

    auto score = [&](const float2& xv) -> float {
        float s;
        s = lrelu(xv.x + xrv.x) * attv.x;
        s = fmaf(lrelu(xv.y + xrv.y), attv.y, s);
        #pragma unroll
        for (int off = 16; off; off >>= 1)
            s += __shfl_xor_sync(0xffffffffu, s, off);
        return __expf(s);
    };
    auto accum = [&](const float2& xv, float p) {
        den += p;
        acc.x = fmaf(p, xv.x, acc.x);
        acc.y = fmaf(p, xv.y, acc.y);
    };

    int j = s0;
    for (; j + 8 <= s1; j += 8) {
        float2 xv[8];
        #pragma unroll
        for (int u = 0; u < 8; u++) {
            int src = g_col[j + u];
            xv[u] = __ldg(&xl2[(size_t)src * 32 + lane]);
        }
        float p[8];
        #pragma unroll
        for (int u = 0; u < 8; u++) p[u] = score(xv[u]);
        #pragma unroll
        for (int u = 0; u < 8; u++) accum(xv[u], p[u]);
    }
    for (; j < s1; j++) {
        int src = g_col[j];
        float2 xv = __ldg(&xl2[(size_t)src * 32 + lane]);
        accum(xv, score(xv));
    }

    float2 bv = *reinterpret_cast<const float2*>(bias + lane * 2);
    float inv = 1.f / den;
    float2 r;
    r.x = fmaf(acc.x, inv, bv.x);
    r.y = fmaf(acc.y, inv, bv.y);
    *reinterpret_cast<float2*>(out + (size_t)v * 64 + lane * 2) = r;
}

// --------------------------- launch ----------------------------------------

extern "C" void kernel_launch(void* const* d_in, const int* in_sizes, int n_in,
                              void* d_out, int out_size) {
    const float* x     = (const float*)d_in[0];
    const int*   ei    = (const int*)d_in[1];
    const float* Wl1   = (const float*)d_in[2];
    const float* bl1   = (const float*)d_in[3];
    const float* Wr1   = (const float*)d_in[4];
    const float* br1   = (const float*)d_in[5];
    const float* att1  = (const float*)d_in[6];
    const float* bias1 = (const float*)d_in[7];
    const float* Wl2   = (const float*)d_in[8];
    const float* bl2   = (const float*)d_in[9];
    const float* Wr2   = (const float*)d_in[10];
    const float* br2   = (const float*)d_in[11];
    const float* att2  = (const float*)d_in[12];
    const float* bias2 = (const float*)d_in[13];
    float* out = (float*)d_out;

    int N = in_sizes[0] / 128;
    int E = in_sizes[1] / 2;
    int total = E + N;
    int rb = (N + 127) / 128;

    // CSR prefix (gemm at position 4 for ncu A/B vs R6)
    k_zero<<<(N + 255) / 256, 256>>>(N);
    k_count<<<(total + 1023) / 1024, 256>>>(ei + E, E, total);
    k_scan<<<1, 1024>>>(N);

    // layer-1 transforms
    k_gemm<0, 0, 128><<<dim3(rb, 2), 256>>>(x, Wl1, bl1, N);
    k_gemm<0, 1, 128><<<dim3(rb, 2), 256>>>(x, Wr1, br1, N);

    // finish CSR
    k_scatter<<<(total + 1023) / 1024, 256>>>(ei, ei + E, E, total);

    // layer-1 aggregation (+ReLU) -> g_h
    k_agg1<<<(N + 7) / 8, 256>>>(att1, bias1, N);

    // layer-2 transforms
    k_gemm<1, 2, 64><<<dim3(rb, 1), 256>>>(nullptr, Wl2, bl2, N);
    k_gemm<1, 3, 64><<<dim3(rb, 1), 256>>>(nullptr, Wr2, br2, N);

    // layer-2 aggregation -> d_out
    k_agg2<<<(N + 7) / 8, 256>>>(att2, bias2, out, N);
}

// round 11
// speedup vs baseline: 1.2166x; 1.2166x over previous
#include <cuda_runtime.h>
#include <cstddef>

// ---------------------------------------------------------------------------
// GATv2 x2 on GB300.  kernel_launch = kernel launches ONLY.
//   1. CSR build by dst (grid-stride atomics — R6 proven)
//   2. fused xl|xr GEMM per layer (f32x2, vectorized k-loads to cut smem
//      crossbar traffic: R8 profile showed L1 70.5% vs fma 44.9%)
//   3. agg layer1 (warp/dst, 4-edge unroll — R6 proven) -> g_h
//   4. fused layer-2 GEMM,  5. agg layer2 -> d_out
// ---------------------------------------------------------------------------

#define NMAX 100000
#define EMAX 1700032

__device__ float g_xl1[NMAX * 128];
__device__ float g_xr1[NMAX * 128];
__device__ float g_h  [NMAX * 128];
__device__ float g_xl2[NMAX * 64];
__device__ float g_xr2[NMAX * 64];
__device__ int   g_deg[NMAX];
__device__ int   g_cnt[NMAX];
__device__ int   g_rowptr[NMAX + 1];
__device__ int   g_col[EMAX];

// --------------------------- CSR build -------------------------------------

__global__ void k_zero(int n) {
    int i = blockIdx.x * blockDim.x + threadIdx.x;
    if (i < n) { g_deg[i] = 0; g_cnt[i] = 0; }
}

__global__ void k_count(const int* __restrict__ dstE, int E, int total) {
    int i = blockIdx.x * blockDim.x + threadIdx.x;
    int stride = gridDim.x * blockDim.x;
    for (; i < total; i += stride) {
        int d = (i < E) ? dstE[i] : (i - E);
        atomicAdd(&g_deg[d], 1);
    }
}

__global__ void k_scan(int n) {
    __shared__ int wsum[32];
    __shared__ int carry;
    int t = threadIdx.x;
    if (t == 0) carry = 0;
    __syncthreads();
    for (int base = 0; base < n; base += 1024) {
        int i = base + t;
        int v = (i < n) ? g_deg[i] : 0;
        int x = v;
        #pragma unroll
        for (int off = 1; off < 32; off <<= 1) {
            int y = __shfl_up_sync(0xffffffffu, x, off);
            if ((t & 31) >= off) x += y;
        }
        if ((t & 31) == 31) wsum[t >> 5] = x;
        __syncthreads();
        if (t < 32) {
            int w = wsum[t];
            #pragma unroll
            for (int off = 1; off < 32; off <<= 1) {
                int y = __shfl_up_sync(0xffffffffu, w, off);
                if (t >= off) w += y;
            }
            wsum[t] = w;
        }
        __syncthreads();
        int incl = x + ((t >= 32) ? wsum[(t >> 5) - 1] : 0);
        if (i < n) g_rowptr[i] = incl - v + carry;
        __syncthreads();
        if (t == 1023) carry += incl;
        __syncthreads();
    }
    if (t == 0) g_rowptr[n] = carry;
}

__global__ void k_scatter(const int* __restrict__ srcE,
                          const int* __restrict__ dstE, int E, int total) {
    int i = blockIdx.x * blockDim.x + threadIdx.x;
    int stride = gridDim.x * blockDim.x;
    for (; i < total; i += stride) {
        int s, d;
        if (i < E) { s = srcE[i]; d = dstE[i]; }
        else       { s = i - E; d = s; }
        int pos = g_rowptr[d] + atomicAdd(&g_cnt[d], 1);
        g_col[pos] = s;
    }
}

// --------------------------- fused dense GEMM -------------------------------
// Computes BOTH xl = X@Wl+bl and xr = X@Wr+br in one launch.
// blockIdx.y in [0, 2*NOUT/64):  lr = y / (NOUT/64),  colgroup = y % (NOUT/64).
// Thread tile 4 rows x 8 cols.  x loaded via LDS.128 (4 k-values at once,
// broadcast among the 8 threads of a row group) -> 4x less x crossbar traffic.

template<int XSEL, int NOUT>
__global__ void __launch_bounds__(256, 3)
k_gemm2(const float* __restrict__ Xarg,
        const float* __restrict__ WL, const float* __restrict__ WR,
        const float* __restrict__ BL, const float* __restrict__ BR, int n) {
    constexpr int K = 128, KC = 64, NB = 64, TPR = 8;
    constexpr int RG = 256 / TPR;                        // 32 row groups
    constexpr int R = 4;
    constexpr int ROWS = RG * R;                         // 128 rows/block
    constexpr int CG = NOUT / NB;                        // col groups per matrix
    __shared__ float sW[KC][NB];          // 16 KB
    __shared__ float sx[ROWS][KC + 4];    // 34 KB (16B-aligned row stride 272B)

    const float* X = (XSEL == 0) ? Xarg : g_h;
    int lr = blockIdx.y / CG;
    int cg = blockIdx.y % CG;
    const float* W    = lr ? WR : WL;
    const float* Bias = lr ? BR : BL;
    float* Y;
    if constexpr (XSEL == 0) Y = lr ? g_xr1 : g_xl1;
    else                     Y = lr ? g_xr2 : g_xl2;

    int tid = threadIdx.x;
    int colOff = cg * NB;
    int c0 = (tid % TPR) * 4;
    int rg = tid / TPR;
    int base = blockIdx.x * ROWS;

    float4 bv0 = *reinterpret_cast<const float4*>(Bias + colOff + c0);
    float4 bv1 = *reinterpret_cast<const float4*>(Bias + colOff + c0 + 32);
    unsigned long long a0[R][2], a1[R][2];
    #pragma unroll
    for (int r = 0; r < R; r++) {
        asm("mov.b64 %0, {%1,%2};" : "=l"(a0[r][0]) : "f"(bv0.x), "f"(bv0.y));
        asm("mov.b64 %0, {%1,%2};" : "=l"(a0[r][1]) : "f"(bv0.z), "f"(bv0.w));
        asm("mov.b64 %0, {%1,%2};" : "=l"(a1[r][0]) : "f"(bv1.x), "f"(bv1.y));
        asm("mov.b64 %0, {%1,%2};" : "=l"(a1[r][1]) : "f"(bv1.z), "f"(bv1.w));
    }

    for (int kc = 0; kc < K; kc += KC) {
        __syncthreads();
        for (int i = tid; i < KC * NB / 4; i += 256) {
            int krow = (i * 4) / NB;
            int col  = (i * 4) % NB;
            *reinterpret_cast<float4*>(&sW[krow][col]) =
                *reinterpret_cast<const float4*>(W + (size_t)(kc + krow) * NOUT + colOff + col);
        }
        for (int i = tid; i < ROWS * (KC / 4); i += 256) {
            int r  = i / (KC / 4);
            int kk = (i % (KC / 4)) * 4;
            int row = base + r;
            float4 v = (row < n)
                ? *reinterpret_cast<const float4*>(X + (size_t)row * K + kc + kk)
                : make_float4(0.f, 0.f, 0.f, 0.f);
            *reinterpret_cast<float4*>(&sx[r][kk]) = v;
        }
        __syncthreads();
        #pragma unroll
        for (int k4 = 0; k4 < KC; k4 += 4) {
            float4 xv[R];
            #pragma unroll
            for (int r = 0; r < R; r++)
                xv[r] = *reinterpret_cast<const float4*>(&sx[rg * R + r][k4]);
            #pragma unroll
            for (int kk = 0; kk < 4; kk++) {
                ulonglong2 w0 = *reinterpret_cast<const ulonglong2*>(&sW[k4 + kk][c0]);
                ulonglong2 w1 = *reinterpret_cast<const ulonglong2*>(&sW[k4 + kk][c0 + 32]);
                #pragma unroll
                for (int r = 0; r < R; r++) {
                    float xs = (kk == 0) ? xv[r].x : (kk == 1) ? xv[r].y
                             : (kk == 2) ? xv[r].z : xv[r].w;
                    unsigned long long x2;
                    asm("mov.b64 %0, {%1,%1};" : "=l"(x2) : "f"(xs));
                    asm("fma.rn.f32x2 %0, %1, %2, %0;" : "+l"(a0[r][0]) : "l"(x2), "l"(w0.x));
                    asm("fma.rn.f32x2 %0, %1, %2, %0;" : "+l"(a0[r][1]) : "l"(x2), "l"(w0.y));
                    asm("fma.rn.f32x2 %0, %1, %2, %0;" : "+l"(a1[r][0]) : "l"(x2), "l"(w1.x));
                    asm("fma.rn.f32x2 %0, %1, %2, %0;" : "+l"(a1[r][1]) : "l"(x2), "l"(w1.y));
                }
            }
        }
    }

    #pragma unroll
    for (int r = 0; r < R; r++) {
        int row = base + rg * R + r;
        if (row < n) {
            float t0, t1, t2, t3;
            asm("mov.b64 {%0,%1}, %2;" : "=f"(t0), "=f"(t1) : "l"(a0[r][0]));
            asm("mov.b64 {%0,%1}, %2;" : "=f"(t2), "=f"(t3) : "l"(a0[r][1]));
            *reinterpret_cast<float4*>(Y + (size_t)row * NOUT + colOff + c0) =
                make_float4(t0, t1, t2, t3);
            asm("mov.b64 {%0,%1}, %2;" : "=f"(t0), "=f"(t1) : "l"(a1[r][0]));
            asm("mov.b64 {%0,%1}, %2;" : "=f"(t2), "=f"(t3) : "l"(a1[r][1]));
            *reinterpret_cast<float4*>(Y + (size_t)row * NOUT + colOff + c0 + 32) =
                make_float4(t0, t1, t2, t3);
        }
    }
}

// --------------------------- GATv2 aggregation ------------------------------
// Warp per destination node (R6 proven form, 4-edge unroll).
// Scores are O(+-10) (glorot x unit-normal): exp without max-pass is safe.

__device__ __forceinline__ float lrelu(float e) {
    return (e > 0.f) ? e : 0.2f * e;
}

__global__ void k_agg1(const float* __restrict__ att, const float* __restrict__ bias,
                       int n) {
    int v    = (blockIdx.x * blockDim.x + threadIdx.x) >> 5;
    int lane = threadIdx.x & 31;
    if (v >= n) return;

    const float4* xl4 = reinterpret_cast<const float4*>(g_xl1);
    float4 xrv  = *reinterpret_cast<const float4*>(g_xr1 + (size_t)v * 128 + lane * 4);
    float4 attv = *reinterpret_cast<const float4*>(att + lane * 4);
    float4 acc  = make_float4(0.f, 0.f, 0.f, 0.f);
    float  den  = 0.f;

    int s0 = g_rowptr[v], s1 = g_rowptr[v + 1];

    auto score = [&](const float4& xv) -> float {
        float s;
        s = lrelu(xv.x + xrv.x) * attv.x;
        s = fmaf(lrelu(xv.y + xrv.y), attv.y, s);
        s = fmaf(lrelu(xv.z + xrv.z), attv.z, s);
        s = fmaf(lrelu(xv.w + xrv.w), attv.w, s);
        s += __shfl_xor_sync(0xffffffffu, s, 1);
        s += __shfl_xor_sync(0xffffffffu, s, 2);
        s += __shfl_xor_sync(0xffffffffu, s, 4);
        return __expf(s);
    };
    auto accum = [&](const float4& xv, float p) {
        den += p;
        acc.x = fmaf(p, xv.x, acc.x);
        acc.y = fmaf(p, xv.y, acc.y);
        acc.z = fmaf(p, xv.z, acc.z);
        acc.w = fmaf(p, xv.w, acc.w);
    };

    int j = s0;
    for (; j + 4 <= s1; j += 4) {
        int i0 = g_col[j], i1 = g_col[j+1], i2 = g_col[j+2], i3 = g_col[j+3];
        float4 x0 = __ldg(&xl4[(size_t)i0 * 32 + lane]);
        float4 x1 = __ldg(&xl4[(size_t)i1 * 32 + lane]);
        float4 x2 = __ldg(&xl4[(size_t)i2 * 32 + lane]);
        float4 x3 = __ldg(&xl4[(size_t)i3 * 32 + lane]);
        float p0 = score(x0), p1 = score(x1), p2 = score(x2), p3 = score(x3);
        accum(x0, p0); accum(x1, p1); accum(x2, p2); accum(x3, p3);
    }
    for (; j < s1; j++) {
        int src = g_col[j];
        float4 xv = __ldg(&xl4[(size_t)src * 32 + lane]);
        accum(xv, score(xv));
    }

    float4 bv = *reinterpret_cast<const float4*>(bias + lane * 4);
    float inv = 1.f / den;
    float4 r;
    r.x = fmaxf(fmaf(acc.x, inv, bv.x), 0.f);
    r.y = fmaxf(fmaf(acc.y, inv, bv.y), 0.f);
    r.z = fmaxf(fmaf(acc.z, inv, bv.z), 0.f);
    r.w = fmaxf(fmaf(acc.w, inv, bv.w), 0.f);
    *reinterpret_cast<float4*>(g_h + (size_t)v * 128 + lane * 4) = r;
}

__global__ void k_agg2(const float* __restrict__ att, const float* __restrict__ bias,
                       float* __restrict__ out, int n) {
    int v    = (blockIdx.x * blockDim.x + threadIdx.x) >> 5;
    int lane = threadIdx.x & 31;
    if (v >= n) return;

    const float2* xl2 = reinterpret_cast<const float2*>(g_xl2);
    float2 xrv  = *reinterpret_cast<const float2*>(g_xr2 + (size_t)v * 64 + lane * 2);
    float2 attv = *reinterpret_cast<const float2*>(att + lane * 2);
    float2 acc  = make_float2(0.f, 0.f);
    float  den  = 0.f;

    int s0 = g_rowptr[v], s1 = g_rowptr[v + 1];

    auto score = [&](const float2& xv) -> float {
        float s;
        s = lrelu(xv.x + xrv.x) * attv.x;
        s = fmaf(lrelu(xv.y + xrv.y), attv.y, s);
        #pragma unroll
        for (int off = 16; off; off >>= 1)
            s += __shfl_xor_sync(0xffffffffu, s, off);
        return __expf(s);
    };
    auto accum = [&](const float2& xv, float p) {
        den += p;
        acc.x = fmaf(p, xv.x, acc.x);
        acc.y = fmaf(p, xv.y, acc.y);
    };

    int j = s0;
    for (; j + 4 <= s1; j += 4) {
        int i0 = g_col[j], i1 = g_col[j+1], i2 = g_col[j+2], i3 = g_col[j+3];
        float2 x0 = __ldg(&xl2[(size_t)i0 * 32 + lane]);
        float2 x1 = __ldg(&xl2[(size_t)i1 * 32 + lane]);
        float2 x2 = __ldg(&xl2[(size_t)i2 * 32 + lane]);
        float2 x3 = __ldg(&xl2[(size_t)i3 * 32 + lane]);
        float p0 = score(x0), p1 = score(x1), p2 = score(x2), p3 = score(x3);
        accum(x0, p0); accum(x1, p1); accum(x2, p2); accum(x3, p3);
    }
    for (; j < s1; j++) {
        int src = g_col[j];
        float2 xv = __ldg(&xl2[(size_t)src * 32 + lane]);
        accum(xv, score(xv));
    }

    float2 bv = *reinterpret_cast<const float2*>(bias + lane * 2);
    float inv = 1.f / den;
    float2 r;
    r.x = fmaf(acc.x, inv, bv.x);
    r.y = fmaf(acc.y, inv, bv.y);
    *reinterpret_cast<float2*>(out + (size_t)v * 64 + lane * 2) = r;
}

// --------------------------- launch ----------------------------------------

extern "C" void kernel_launch(void* const* d_in, const int* in_sizes, int n_in,
                              void* d_out, int out_size) {
    const float* x     = (const float*)d_in[0];
    const int*   ei    = (const int*)d_in[1];
    const float* Wl1   = (const float*)d_in[2];
    const float* bl1   = (const float*)d_in[3];
    const float* Wr1   = (const float*)d_in[4];
    const float* br1   = (const float*)d_in[5];
    const float* att1  = (const float*)d_in[6];
    const float* bias1 = (const float*)d_in[7];
    const float* Wl2   = (const float*)d_in[8];
    const float* bl2   = (const float*)d_in[9];
    const float* Wr2   = (const float*)d_in[10];
    const float* br2   = (const float*)d_in[11];
    const float* att2  = (const float*)d_in[12];
    const float* bias2 = (const float*)d_in[13];
    float* out = (float*)d_out;

    int N = in_sizes[0] / 128;
    int E = in_sizes[1] / 2;
    int total = E + N;
    int rb = (N + 127) / 128;

    // CSR prefix (fused gemm sits at launch position 4 for ncu capture)
    k_zero<<<(N + 255) / 256, 256>>>(N);
    k_count<<<2048, 256>>>(ei + E, E, total);
    k_scan<<<1, 1024>>>(N);

    // layer-1 fused transform: y = (l/r) x (2 col groups) = 4
    k_gemm2<0, 128><<<dim3(rb, 4), 256>>>(x, Wl1, Wr1, bl1, br1, N);

    // finish CSR
    k_scatter<<<2048, 256>>>(ei, ei + E, E, total);

    // layer-1 aggregation (+ReLU) -> g_h
    k_agg1<<<(N + 7) / 8, 256>>>(att1, bias1, N);

    // layer-2 fused transform: y = (l/r) x (1 col group) = 2
    k_gemm2<1, 64><<<dim3(rb, 2), 256>>>(nullptr, Wl2, Wr2, bl2, br2, N);

    // layer-2 aggregation -> d_out
    k_agg2<<<(N + 7) / 8, 256>>>(att2, bias2, out, N);
}

// round 12
// speedup vs baseline: 1.2436x; 1.0222x over previous
#include <cuda_runtime.h>
#include <cstddef>

// ---------------------------------------------------------------------------
// GATv2 x2 on GB300.  kernel_launch = kernel launches ONLY.
//   1. CSR build by dst (int4-vectorized atomics; self-loops folded into
//      zero-seed + scatter tail)
//   2. fused xl|xr GEMM per layer: 8 rows x 8 cols per thread, interleaved
//      row mapping (bank-conflict-free) -> fma-pipe-bound (R11: L1 87% bound)
//   3. agg layer1 (warp/dst, 4-edge unroll — proven) -> g_h
//   4. fused layer-2 GEMM,  5. agg layer2 -> d_out
// ---------------------------------------------------------------------------

#define NMAX 100000
#define EMAX 1700032

__device__ float g_xl1[NMAX * 128];
__device__ float g_xr1[NMAX * 128];
__device__ float g_h  [NMAX * 128];
__device__ float g_xl2[NMAX * 64];
__device__ float g_xr2[NMAX * 64];
__device__ int   g_deg[NMAX];
__device__ int   g_cnt[NMAX];
__device__ int   g_rowptr[NMAX + 1];
__device__ int   g_col[EMAX];

// --------------------------- CSR build -------------------------------------

// seed deg=1: self-loop contribution pre-counted
__global__ void k_zero(int n) {
    int i = blockIdx.x * blockDim.x + threadIdx.x;
    if (i < n) { g_deg[i] = 1; g_cnt[i] = 0; }
}

// nvec = E/4 if 16B-aligned vectorization valid, else 0 (scalar fallback)
__global__ void k_count(const int* __restrict__ dstE, int E, int nvec) {
    int t = blockIdx.x * blockDim.x + threadIdx.x;
    if (t < nvec) {
        int4 d = reinterpret_cast<const int4*>(dstE)[t];
        atomicAdd(&g_deg[d.x], 1);
        atomicAdd(&g_deg[d.y], 1);
        atomicAdd(&g_deg[d.z], 1);
        atomicAdd(&g_deg[d.w], 1);
    } else {
        int e = nvec * 4 + (t - nvec);
        if (e < E) atomicAdd(&g_deg[dstE[e]], 1);
    }
}

__global__ void k_scan(int n) {
    __shared__ int wsum[32];
    __shared__ int carry;
    int t = threadIdx.x;
    if (t == 0) carry = 0;
    __syncthreads();
    for (int base = 0; base < n; base += 1024) {
        int i = base + t;
        int v = (i < n) ? g_deg[i] : 0;
        int x = v;
        #pragma unroll
        for (int off = 1; off < 32; off <<= 1) {
            int y = __shfl_up_sync(0xffffffffu, x, off);
            if ((t & 31) >= off) x += y;
        }
        if ((t & 31) == 31) wsum[t >> 5] = x;
        __syncthreads();
        if (t < 32) {
            int w = wsum[t];
            #pragma unroll
            for (int off = 1; off < 32; off <<= 1) {
                int y = __shfl_up_sync(0xffffffffu, w, off);
                if (t >= off) w += y;
            }
            wsum[t] = w;
        }
        __syncthreads();
        int incl = x + ((t >= 32) ? wsum[(t >> 5) - 1] : 0);
        if (i < n) g_rowptr[i] = incl - v + carry;
        __syncthreads();
        if (t == 1023) carry += incl;
        __syncthreads();
    }
    if (t == 0) g_rowptr[n] = carry;
}

__device__ __forceinline__ void csr_place(int s, int d) {
    int pos = g_rowptr[d] + atomicAdd(&g_cnt[d], 1);
    g_col[pos] = s;
}

// threads: [0,nvec) vec edges; [nvec,nvec+N) self loops; then scalar edge tail
__global__ void k_scatter(const int* __restrict__ srcE,
                          const int* __restrict__ dstE, int E, int nvec, int N) {
    int t = blockIdx.x * blockDim.x + threadIdx.x;
    if (t < nvec) {
        int4 s = reinterpret_cast<const int4*>(srcE)[t];
        int4 d = reinterpret_cast<const int4*>(dstE)[t];
        csr_place(s.x, d.x);
        csr_place(s.y, d.y);
        csr_place(s.z, d.z);
        csr_place(s.w, d.w);
    } else {
        int u = t - nvec;
        if (u < N) {
            csr_place(u, u);
        } else {
            int e = nvec * 4 + (u - N);
            if (e < E) csr_place(srcE[e], dstE[e]);
        }
    }
}

// --------------------------- fused dense GEMM -------------------------------
// Computes BOTH xl = X@Wl+bl and xr = X@Wr+br in one launch.
// 128 threads/block, thread tile 8 rows x 8 cols, rows interleaved rg + r*16
// (x-load banks conflict-free).  Per warp per k: 32 FFMA2 + 8 mov + 4 LDS.128
// = 44 issues vs 64 fma-cycles -> fma-pipe-bound.

template<int XSEL, int NOUT>
__global__ void __launch_bounds__(128, 4)
k_gemm2(const float* __restrict__ Xarg,
        const float* __restrict__ WL, const float* __restrict__ WR,
        const float* __restrict__ BL, const float* __restrict__ BR, int n) {
    constexpr int K = 128, KC = 64, NB = 64, TPR = 8;
    constexpr int RG = 128 / TPR;                        // 16 row groups
    constexpr int R = 8;
    constexpr int ROWS = RG * R;                         // 128 rows/block
    constexpr int CG = NOUT / NB;
    __shared__ float sW[KC][NB];          // 16 KB
    __shared__ float sx[ROWS][KC + 4];    // 34.8 KB

    const float* X = (XSEL == 0) ? Xarg : g_h;
    int lr = blockIdx.y / CG;
    int cg = blockIdx.y % CG;
    const float* W    = lr ? WR : WL;
    const float* Bias = lr ? BR : BL;
    float* Y;
    if constexpr (XSEL == 0) Y = lr ? g_xr1 : g_xl1;
    else                     Y = lr ? g_xr2 : g_xl2;

    int tid = threadIdx.x;
    int colOff = cg * NB;
    int c0 = (tid % TPR) * 4;
    int rg = tid / TPR;                  // 0..15
    int base = blockIdx.x * ROWS;

    float4 bv0 = *reinterpret_cast<const float4*>(Bias + colOff + c0);
    float4 bv1 = *reinterpret_cast<const float4*>(Bias + colOff + c0 + 32);
    unsigned long long a0[R][2], a1[R][2];
    #pragma unroll
    for (int r = 0; r < R; r++) {
        asm("mov.b64 %0, {%1,%2};" : "=l"(a0[r][0]) : "f"(bv0.x), "f"(bv0.y));
        asm("mov.b64 %0, {%1,%2};" : "=l"(a0[r][1]) : "f"(bv0.z), "f"(bv0.w));
        asm("mov.b64 %0, {%1,%2};" : "=l"(a1[r][0]) : "f"(bv1.x), "f"(bv1.y));
        asm("mov.b64 %0, {%1,%2};" : "=l"(a1[r][1]) : "f"(bv1.z), "f"(bv1.w));
    }

    for (int kc = 0; kc < K; kc += KC) {
        __syncthreads();
        for (int i = tid; i < KC * NB / 4; i += 128) {
            int krow = (i * 4) / NB;
            int col  = (i * 4) % NB;
            *reinterpret_cast<float4*>(&sW[krow][col]) =
                *reinterpret_cast<const float4*>(W + (size_t)(kc + krow) * NOUT + colOff + col);
        }
        for (int i = tid; i < ROWS * (KC / 4); i += 128) {
            int r  = i / (KC / 4);
            int kk = (i % (KC / 4)) * 4;
            int row = base + r;
            float4 v = (row < n)
                ? *reinterpret_cast<const float4*>(X + (size_t)row * K + kc + kk)
                : make_float4(0.f, 0.f, 0.f, 0.f);
            *reinterpret_cast<float4*>(&sx[r][kk]) = v;
        }
        __syncthreads();
        #pragma unroll
        for (int k4 = 0; k4 < KC; k4 += 4) {
            float4 xv[R];
            #pragma unroll
            for (int r = 0; r < R; r++)
                xv[r] = *reinterpret_cast<const float4*>(&sx[rg + r * RG][k4]);
            #pragma unroll
            for (int kk = 0; kk < 4; kk++) {
                ulonglong2 w0 = *reinterpret_cast<const ulonglong2*>(&sW[k4 + kk][c0]);
                ulonglong2 w1 = *reinterpret_cast<const ulonglong2*>(&sW[k4 + kk][c0 + 32]);
                #pragma unroll
                for (int r = 0; r < R; r++) {
                    float xs = (kk == 0) ? xv[r].x : (kk == 1) ? xv[r].y
                             : (kk == 2) ? xv[r].z : xv[r].w;
                    unsigned long long x2;
                    asm("mov.b64 %0, {%1,%1};" : "=l"(x2) : "f"(xs));
                    asm("fma.rn.f32x2 %0, %1, %2, %0;" : "+l"(a0[r][0]) : "l"(x2), "l"(w0.x));
                    asm("fma.rn.f32x2 %0, %1, %2, %0;" : "+l"(a0[r][1]) : "l"(x2), "l"(w0.y));
                    asm("fma.rn.f32x2 %0, %1, %2, %0;" : "+l"(a1[r][0]) : "l"(x2), "l"(w1.x));
                    asm("fma.rn.f32x2 %0, %1, %2, %0;" : "+l"(a1[r][1]) : "l"(x2), "l"(w1.y));
                }
            }
        }
    }

    #pragma unroll
    for (int r = 0; r < R; r++) {
        int row = base + rg + r * RG;
        if (row < n) {
            float t0, t1, t2, t3;
            asm("mov.b64 {%0,%1}, %2;" : "=f"(t0), "=f"(t1) : "l"(a0[r][0]));
            asm("mov.b64 {%0,%1}, %2;" : "=f"(t2), "=f"(t3) : "l"(a0[r][1]));
            *reinterpret_cast<float4*>(Y + (size_t)row * NOUT + colOff + c0) =
                make_float4(t0, t1, t2, t3);
            asm("mov.b64 {%0,%1}, %2;" : "=f"(t0), "=f"(t1) : "l"(a1[r][0]));
            asm("mov.b64 {%0,%1}, %2;" : "=f"(t2), "=f"(t3) : "l"(a1[r][1]));
            *reinterpret_cast<float4*>(Y + (size_t)row * NOUT + colOff + c0 + 32) =
                make_float4(t0, t1, t2, t3);
        }
    }
}

// --------------------------- GATv2 aggregation ------------------------------
// Warp per destination node (proven form, 4-edge unroll).
// Scores are O(+-10) (glorot x unit-normal): exp without max-pass is safe.

__device__ __forceinline__ float lrelu(float e) {
    return (e > 0.f) ? e : 0.2f * e;
}

__global__ void k_agg1(const float* __restrict__ att, const float* __restrict__ bias,
                       int n) {
    int v    = (blockIdx.x * blockDim.x + threadIdx.x) >> 5;
    int lane = threadIdx.x & 31;
    if (v >= n) return;

    const float4* xl4 = reinterpret_cast<const float4*>(g_xl1);
    float4 xrv  = *reinterpret_cast<const float4*>(g_xr1 + (size_t)v * 128 + lane * 4);
    float4 attv = *reinterpret_cast<const float4*>(att + lane * 4);
    float4 acc  = make_float4(0.f, 0.f, 0.f, 0.f);
    float  den  = 0.f;

    int s0 = g_rowptr[v], s1 = g_rowptr[v + 1];

    auto score = [&](const float4& xv) -> float {
        float s;
        s = lrelu(xv.x + xrv.x) * attv.x;
        s = fmaf(lrelu(xv.y + xrv.y), attv.y, s);
        s = fmaf(lrelu(xv.z + xrv.z), attv.z, s);
        s = fmaf(lrelu(xv.w + xrv.w), attv.w, s);
        s += __shfl_xor_sync(0xffffffffu, s, 1);
        s += __shfl_xor_sync(0xffffffffu, s, 2);
        s += __shfl_xor_sync(0xffffffffu, s, 4);
        return __expf(s);
    };
    auto accum = [&](const float4& xv, float p) {
        den += p;
        acc.x = fmaf(p, xv.x, acc.x);
        acc.y = fmaf(p, xv.y, acc.y);
        acc.z = fmaf(p, xv.z, acc.z);
        acc.w = fmaf(p, xv.w, acc.w);
    };

    int j = s0;
    for (; j + 4 <= s1; j += 4) {
        int i0 = g_col[j], i1 = g_col[j+1], i2 = g_col[j+2], i3 = g_col[j+3];
        float4 x0 = __ldg(&xl4[(size_t)i0 * 32 + lane]);
        float4 x1 = __ldg(&xl4[(size_t)i1 * 32 + lane]);
        float4 x2 = __ldg(&xl4[(size_t)i2 * 32 + lane]);
        float4 x3 = __ldg(&xl4[(size_t)i3 * 32 + lane]);
        float p0 = score(x0), p1 = score(x1), p2 = score(x2), p3 = score(x3);
        accum(x0, p0); accum(x1, p1); accum(x2, p2); accum(x3, p3);
    }
    for (; j < s1; j++) {
        int src = g_col[j];
        float4 xv = __ldg(&xl4[(size_t)src * 32 + lane]);
        accum(xv, score(xv));
    }

    float4 bv = *reinterpret_cast<const float4*>(bias + lane * 4);
    float inv = 1.f / den;
    float4 r;
    r.x = fmaxf(fmaf(acc.x, inv, bv.x), 0.f);
    r.y = fmaxf(fmaf(acc.y, inv, bv.y), 0.f);
    r.z = fmaxf(fmaf(acc.z, inv, bv.z), 0.f);
    r.w = fmaxf(fmaf(acc.w, inv, bv.w), 0.f);
    *reinterpret_cast<float4*>(g_h + (size_t)v * 128 + lane * 4) = r;
}

__global__ void k_agg2(const float* __restrict__ att, const float* __restrict__ bias,
                       float* __restrict__ out, int n) {
    int v    = (blockIdx.x * blockDim.x + threadIdx.x) >> 5;
    int lane = threadIdx.x & 31;
    if (v >= n) return;

    const float2* xl2 = reinterpret_cast<const float2*>(g_xl2);
    float2 xrv  = *reinterpret_cast<const float2*>(g_xr2 + (size_t)v * 64 + lane * 2);
    float2 attv = *reinterpret_cast<const float2*>(att + lane * 2);
    float2 acc  = make_float2(0.f, 0.f);
    float  den  = 0.f;

    int s0 = g_rowptr[v], s1 = g_rowptr[v + 1];

    auto score = [&](const float2& xv) -> float {
        float s;
        s = lrelu(xv.x + xrv.x) * attv.x;
        s = fmaf(lrelu(xv.y + xrv.y), attv.y, s);
        #pragma unroll
        for (int off = 16; off; off >>= 1)
            s += __shfl_xor_sync(0xffffffffu, s, off);
        return __expf(s);
    };
    auto accum = [&](const float2& xv, float p) {
        den += p;
        acc.x = fmaf(p, xv.x, acc.x);
        acc.y = fmaf(p, xv.y, acc.y);
    };

    int j = s0;
    for (; j + 4 <= s1; j += 4) {
        int i0 = g_col[j], i1 = g_col[j+1], i2 = g_col[j+2], i3 = g_col[j+3];
        float2 x0 = __ldg(&xl2[(size_t)i0 * 32 + lane]);
        float2 x1 = __ldg(&xl2[(size_t)i1 * 32 + lane]);
        float2 x2 = __ldg(&xl2[(size_t)i2 * 32 + lane]);
        float2 x3 = __ldg(&xl2[(size_t)i3 * 32 + lane]);
        float p0 = score(x0), p1 = score(x1), p2 = score(x2), p3 = score(x3);
        accum(x0, p0); accum(x1, p1); accum(x2, p2); accum(x3, p3);
    }
    for (; j < s1; j++) {
        int src = g_col[j];
        float2 xv = __ldg(&xl2[(size_t)src * 32 + lane]);
        accum(xv, score(xv));
    }

    float2 bv = *reinterpret_cast<const float2*>(bias + lane * 2);
    float inv = 1.f / den;
    float2 r;
    r.x = fmaf(acc.x, inv, bv.x);
    r.y = fmaf(acc.y, inv, bv.y);
    *reinterpret_cast<float2*>(out + (size_t)v * 64 + lane * 2) = r;
}

// --------------------------- launch ----------------------------------------

extern "C" void kernel_launch(void* const* d_in, const int* in_sizes, int n_in,
                              void* d_out, int out_size) {
    const float* x     = (const float*)d_in[0];
    const int*   ei    = (const int*)d_in[1];
    const float* Wl1   = (const float*)d_in[2];
    const float* bl1   = (const float*)d_in[3];
    const float* Wr1   = (const float*)d_in[4];
    const float* br1   = (const float*)d_in[5];
    const float* att1  = (const float*)d_in[6];
    const float* bias1 = (const float*)d_in[7];
    const float* Wl2   = (const float*)d_in[8];
    const float* bl2   = (const float*)d_in[9];
    const float* Wr2   = (const float*)d_in[10];
    const float* br2   = (const float*)d_in[11];
    const float* att2  = (const float*)d_in[12];
    const float* bias2 = (const float*)d_in[13];
    float* out = (float*)d_out;

    int N = in_sizes[0] / 128;
    int E = in_sizes[1] / 2;
    int rb = (N + 127) / 128;
    // vectorize only if edge array halves stay 16B-aligned
    int nvec = ((E & 3) == 0) ? (E >> 2) : 0;

    // CSR prefix (gemm1 is 4th launch -> ncu capture)
    k_zero<<<(N + 255) / 256, 256>>>(N);
    {
        int th = nvec + (E - nvec * 4);
        k_count<<<(th + 255) / 256, 256>>>(ei + E, E, nvec);
    }
    k_scan<<<1, 1024>>>(N);

    // layer-1 fused transform: y = (l/r) x (2 col groups) = 4
    k_gemm2<0, 128><<<dim3(rb, 4), 128>>>(x, Wl1, Wr1, bl1, br1, N);

    // finish CSR (self loops included in tail)
    {
        int th = nvec + N + (E - nvec * 4);
        k_scatter<<<(th + 255) / 256, 256>>>(ei, ei + E, E, nvec, N);
    }

    // layer-1 aggregation (+ReLU) -> g_h
    k_agg1<<<(N + 7) / 8, 256>>>(att1, bias1, N);

    // layer-2 fused transform: y = (l/r) x (1 col group) = 2
    k_gemm2<1, 64><<<dim3(rb, 2), 128>>>(nullptr, Wl2, Wr2, bl2, br2, N);

    // layer-2 aggregation -> d_out
    k_agg2<<<(N + 7) / 8, 256>>>(att2, bias2, out, N);
}